// round 7
// baseline (speedup 1.0000x reference)
#include <cuda_runtime.h>
#include <stdint.h>

#define N_RAYS    32768
#define N_OBJ     16
#define N_SAMPLES 32
#define N_BASE    64
#define N_Z       (N_OBJ * N_SAMPLES)     // 512
#define TOTAL     (N_BASE + N_Z)          // 576
#define SORT_N    1024
#define MISS      1e10f

// ---- scratch (__device__ globals: allocation-free) ----
__device__ float         g_R [N_OBJ][9];
__device__ float         g_T [N_OBJ][3];
__device__ float         g_iR[N_OBJ][9];
__device__ float         g_iT[N_OBJ][3];
__device__ float         g_z [(size_t)N_RAYS * N_Z];     // 64 MB
__device__ unsigned char g_hit[(size_t)N_RAYS * N_OBJ];  // 512 KB

// XLA-GPU lowers x/sqrt(s) -> x * rsqrt(s) with rsqrt.approx.f32.
__device__ __forceinline__ float rsqrt_approx(float x) {
    float r;
    asm("rsqrt.approx.f32 %0, %1;" : "=f"(r) : "f"(x));
    return r;
}

// ---------------------------------------------------------------------------
// Kernel 0: pt_mat = trafos @ scales (diagonal scales => single-rounded
// products). Inverse computed exactly in fp64, rounded to fp32.
// ---------------------------------------------------------------------------
__global__ void precompute_kernel(const float* __restrict__ trafos,
                                  const float* __restrict__ scales) {
    int m = threadIdx.x;
    if (m >= N_OBJ) return;
    const float* A = trafos + m * 16;
    const float* B = scales + m * 16;
    float s0 = B[0], s1 = B[5], s2 = B[10];
    float R[9], T[3];
    #pragma unroll
    for (int i = 0; i < 3; i++) {
        R[i * 3 + 0] = __fmul_rn(A[i * 4 + 0], s0);
        R[i * 3 + 1] = __fmul_rn(A[i * 4 + 1], s1);
        R[i * 3 + 2] = __fmul_rn(A[i * 4 + 2], s2);
    }
    T[0] = __fmul_rn(A[12], s0);
    T[1] = __fmul_rn(A[13], s1);
    T[2] = __fmul_rn(A[14], s2);

    double a = R[0], b = R[1], c = R[2];
    double d = R[3], e = R[4], f = R[5];
    double g = R[6], h = R[7], i = R[8];
    double A0 = e * i - f * h, B0 = -(d * i - f * g), C0 = d * h - e * g;
    double D0 = -(b * i - c * h), E0 = a * i - c * g, F0 = -(a * h - b * g);
    double G0 = b * f - c * e, H0 = -(a * f - c * d), I0 = a * e - b * d;
    double det = a * A0 + b * B0 + c * C0;
    double id = 1.0 / det;
    double iR[9] = { A0 * id, D0 * id, G0 * id,
                     B0 * id, E0 * id, H0 * id,
                     C0 * id, F0 * id, I0 * id };
    double iT[3];
    #pragma unroll
    for (int j = 0; j < 3; j++)
        iT[j] = -((double)T[0] * iR[0 + j] + (double)T[1] * iR[3 + j]
                  + (double)T[2] * iR[6 + j]);

    #pragma unroll
    for (int k = 0; k < 9; k++) { g_R[m][k] = R[k]; g_iR[m][k] = (float)iR[k]; }
    #pragma unroll
    for (int k = 0; k < 3; k++) { g_T[m][k] = T[k]; g_iT[m][k] = (float)iT[k]; }
}

// fma-chain contraction, ascending k.
__device__ __forceinline__ float dot3_fma(float x0, float x1, float x2,
                                          float m0, float m1, float m2) {
    return fmaf(x2, m2, fmaf(x1, m1, __fmul_rn(x0, m0)));
}

__global__ void __launch_bounds__(128)
sample_kernel(const float* __restrict__ origins,
              const float* __restrict__ directions,
              float* __restrict__ out_pts,
              float* __restrict__ out_dirs) {
    int gw   = (blockIdx.x * blockDim.x + threadIdx.x) >> 5;
    int lane = threadIdx.x & 31;
    int m = gw >> 15;            // gw / N_RAYS
    int n = gw & (N_RAYS - 1);

    float ox = __ldg(origins + 3 * n + 0);
    float oy = __ldg(origins + 3 * n + 1);
    float oz = __ldg(origins + 3 * n + 2);
    float dx = __ldg(directions + 3 * n + 0);
    float dy = __ldg(directions + 3 * n + 1);
    float dz = __ldg(directions + 3 * n + 2);

    // d_w = directions * rsqrt.approx(sumsq)   (XLA a/sqrt(b) -> a*rsqrt(b))
    float dss = __fadd_rn(__fadd_rn(__fmul_rn(dx, dx), __fmul_rn(dy, dy)),
                          __fmul_rn(dz, dz));
    float drs = rsqrt_approx(dss);
    float dwx = __fmul_rn(dx, drs), dwy = __fmul_rn(dy, drs), dwz = __fmul_rn(dz, drs);

    const float* R = g_R[m];
    const float* T = g_T[m];
    float oo0 = __fadd_rn(dot3_fma(ox, oy, oz, R[0], R[3], R[6]), T[0]);
    float oo1 = __fadd_rn(dot3_fma(ox, oy, oz, R[1], R[4], R[7]), T[1]);
    float oo2 = __fadd_rn(dot3_fma(ox, oy, oz, R[2], R[5], R[8]), T[2]);
    float dr0 = dot3_fma(dwx, dwy, dwz, R[0], R[3], R[6]);
    float dr1 = dot3_fma(dwx, dwy, dwz, R[1], R[4], R[7]);
    float dr2 = dot3_fma(dwx, dwy, dwz, R[2], R[5], R[8]);
    // dirs_o = dr * rsqrt.approx(sumsq)
    float oss = __fadd_rn(__fadd_rn(__fmul_rn(dr0, dr0), __fmul_rn(dr1, dr1)),
                          __fmul_rn(dr2, dr2));
    float ors = rsqrt_approx(oss);
    float do0 = __fmul_rn(dr0, ors), do1 = __fmul_rn(dr1, ors), do2 = __fmul_rn(dr2, ors);

    float i0 = __fdiv_rn(1.f, do0), i1 = __fdiv_rn(1.f, do1), i2 = __fdiv_rn(1.f, do2);
    float t0x = __fmul_rn(__fsub_rn(-1.f, oo0), i0), t1x = __fmul_rn(__fsub_rn(1.f, oo0), i0);
    float t0y = __fmul_rn(__fsub_rn(-1.f, oo1), i1), t1y = __fmul_rn(__fsub_rn(1.f, oo1), i1);
    float t0z = __fmul_rn(__fsub_rn(-1.f, oo2), i2), t1z = __fmul_rn(__fsub_rn(1.f, oo2), i2);
    float tmin = fmaxf(fmaxf(fminf(t0x, t1x), fminf(t0y, t1y)), fminf(t0z, t1z));
    float tmax = fminf(fminf(fmaxf(t0x, t1x), fmaxf(t0y, t1y)), fmaxf(t0z, t1z));
    bool hit = (tmax > tmin) && (tmax > 0.f);
    float tin = fmaxf(tmin, 0.f);
    float hf  = hit ? 1.f : 0.f;

    // linspace(0,1,32): correctly-rounded s/31 per lane
    float lin = __fdiv_rn((float)lane, 31.0f);
    float zo  = __fadd_rn(tin, __fmul_rn(__fsub_rn(tmax, tin), lin));
    float p0 = __fadd_rn(oo0, __fmul_rn(do0, zo));
    float p1 = __fadd_rn(oo1, __fmul_rn(do1, zo));
    float p2 = __fadd_rn(oo2, __fmul_rn(do2, zo));

    size_t base = ((size_t)(m * N_RAYS + n) * N_SAMPLES + lane) * 3;
    out_pts [base + 0] = __fmul_rn(p0, hf);
    out_pts [base + 1] = __fmul_rn(p1, hf);
    out_pts [base + 2] = __fmul_rn(p2, hf);
    out_dirs[base + 0] = __fmul_rn(do0, hf);
    out_dirs[base + 1] = __fmul_rn(do1, hf);
    out_dirs[base + 2] = __fmul_rn(do2, hf);

    const float* iR = g_iR[m];
    const float* iT = g_iT[m];
    float w0 = __fadd_rn(dot3_fma(p0, p1, p2, iR[0], iR[3], iR[6]), iT[0]);
    float w1 = __fadd_rn(dot3_fma(p0, p1, p2, iR[1], iR[4], iR[7]), iT[1]);
    float w2 = __fadd_rn(dot3_fma(p0, p1, p2, iR[2], iR[5], iR[8]), iT[2]);
    float q0 = __fsub_rn(w0, ox), q1 = __fsub_rn(w1, oy), q2 = __fsub_rn(w2, oz);
    float zw = dot3_fma(q0, q1, q2, dwx, dwy, dwz);

    g_z[(size_t)n * N_Z + m * N_SAMPLES + lane] = hit ? zw : MISS;
    if (lane == 0) g_hit[(size_t)n * N_OBJ + m] = hit ? 1 : 0;
}

// ---------------------------------------------------------------------------
// Kernel 2: per-ray stable sort of 576 keys (padded to 1024, bitonic).
// ---------------------------------------------------------------------------
__device__ __forceinline__ unsigned float_to_ord(float f) {
    unsigned u = __float_as_uint(f);
    return (u & 0x80000000u) ? ~u : (u | 0x80000000u);
}
__device__ __forceinline__ float ord_to_float(unsigned u) {
    return (u & 0x80000000u) ? __uint_as_float(u ^ 0x80000000u)
                             : __uint_as_float(~u);
}

__global__ void __launch_bounds__(512)
sort_kernel(const float* __restrict__ lengths,
            float* __restrict__ out_len,
            float* __restrict__ out_node,
            float* __restrict__ out_mask) {
    __shared__ unsigned long long sk[SORT_N];
    __shared__ unsigned char sh_hit[N_OBJ];
    int n = blockIdx.x;
    int tid = threadIdx.x;

    if (tid < N_OBJ) sh_hit[tid] = g_hit[(size_t)n * N_OBJ + tid];

    #pragma unroll
    for (int q = 0; q < 2; q++) {
        int i = tid + q * 512;
        unsigned long long key;
        if (i < N_BASE) {
            float f = lengths[(size_t)n * N_BASE + i];
            key = ((unsigned long long)float_to_ord(f) << 32) | (unsigned)i;
        } else if (i < TOTAL) {
            float f = g_z[(size_t)n * N_Z + (i - N_BASE)];
            key = ((unsigned long long)float_to_ord(f) << 32) | (unsigned)i;
        } else {
            key = 0xFFFFFFFFFFFFFFFFull;
        }
        sk[i] = key;
    }
    __syncthreads();

    for (int k = 2; k <= SORT_N; k <<= 1) {
        for (int j = k >> 1; j > 0; j >>= 1) {
            #pragma unroll
            for (int q = 0; q < 2; q++) {
                int i = tid + q * 512;
                int ixj = i ^ j;
                if (ixj > i) {
                    unsigned long long a = sk[i], b = sk[ixj];
                    bool up = ((i & k) == 0);
                    if ((a > b) == up) { sk[i] = b; sk[ixj] = a; }
                }
            }
            __syncthreads();
        }
    }

    #pragma unroll
    for (int q = 0; q < 2; q++) {
        int i = tid + q * 512;
        if (i < TOTAL) {
            unsigned long long key = sk[i];
            float f = ord_to_float((unsigned)(key >> 32));
            int j = (int)(key & 0x3FFu);
            int node = -1; float mask = 0.f;
            if (j >= N_BASE) {
                int mm = (j - N_BASE) >> 5;
                if (sh_hit[mm]) { node = mm; mask = 1.f; }
            }
            size_t ob = (size_t)n * TOTAL + i;
            out_len [ob] = f;
            out_node[ob] = (float)node;
            out_mask[ob] = mask;
        }
    }
}

// ---------------------------------------------------------------------------
extern "C" void kernel_launch(void* const* d_in, const int* in_sizes, int n_in,
                              void* d_out, int out_size) {
    const float* origins    = (const float*)d_in[0];
    const float* directions = (const float*)d_in[1];
    const float* lengths    = (const float*)d_in[2];
    const float* trafos     = (const float*)d_in[3];
    // d_in[4] = rots_w2o unused (composed linear part identical to trafos@scales)
    const float* scales     = (const float*)d_in[5];

    float* out = (float*)d_out;
    size_t nc = (size_t)N_RAYS * TOTAL;
    float* o_len  = out;
    float* o_node = out + nc;
    float* o_mask = out + 2 * nc;
    float* o_pts  = out + 3 * nc;
    float* o_dirs = o_pts + (size_t)N_OBJ * N_RAYS * N_SAMPLES * 3;

    precompute_kernel<<<1, 32>>>(trafos, scales);

    int total_warps = N_OBJ * N_RAYS;               // 524288
    sample_kernel<<<total_warps / 4, 128>>>(origins, directions, o_pts, o_dirs);

    sort_kernel<<<N_RAYS, 512>>>(lengths, o_len, o_node, o_mask);
}

// round 8
// speedup vs baseline: 1.5277x; 1.5277x over previous
#include <cuda_runtime.h>
#include <stdint.h>

#define N_RAYS    32768
#define N_OBJ     16
#define N_SAMPLES 32
#define N_BASE    64
#define TOTAL     (N_BASE + N_OBJ * N_SAMPLES)   // 576
#define MISS      1e10f

// ---- per-object transform constants ----
__device__ float g_R [N_OBJ][9];
__device__ float g_T [N_OBJ][3];
__device__ float g_iR[N_OBJ][9];
__device__ float g_iT[N_OBJ][3];

// XLA-GPU lowers x/sqrt(s) -> x * rsqrt(s) with rsqrt.approx.f32.
__device__ __forceinline__ float rsqrt_approx(float x) {
    float r;
    asm("rsqrt.approx.f32 %0, %1;" : "=f"(r) : "f"(x));
    return r;
}

// ---------------------------------------------------------------------------
// Kernel 0: pt_mat = trafos @ scales; inverse exact in fp64, rounded to fp32.
// (bit-identical to Round 7 — DO NOT TOUCH)
// ---------------------------------------------------------------------------
__global__ void precompute_kernel(const float* __restrict__ trafos,
                                  const float* __restrict__ scales) {
    int m = threadIdx.x;
    if (m >= N_OBJ) return;
    const float* A = trafos + m * 16;
    const float* B = scales + m * 16;
    float s0 = B[0], s1 = B[5], s2 = B[10];
    float R[9], T[3];
    #pragma unroll
    for (int i = 0; i < 3; i++) {
        R[i * 3 + 0] = __fmul_rn(A[i * 4 + 0], s0);
        R[i * 3 + 1] = __fmul_rn(A[i * 4 + 1], s1);
        R[i * 3 + 2] = __fmul_rn(A[i * 4 + 2], s2);
    }
    T[0] = __fmul_rn(A[12], s0);
    T[1] = __fmul_rn(A[13], s1);
    T[2] = __fmul_rn(A[14], s2);

    double a = R[0], b = R[1], c = R[2];
    double d = R[3], e = R[4], f = R[5];
    double g = R[6], h = R[7], i = R[8];
    double A0 = e * i - f * h, B0 = -(d * i - f * g), C0 = d * h - e * g;
    double D0 = -(b * i - c * h), E0 = a * i - c * g, F0 = -(a * h - b * g);
    double G0 = b * f - c * e, H0 = -(a * f - c * d), I0 = a * e - b * d;
    double det = a * A0 + b * B0 + c * C0;
    double id = 1.0 / det;
    double iR[9] = { A0 * id, D0 * id, G0 * id,
                     B0 * id, E0 * id, H0 * id,
                     C0 * id, F0 * id, I0 * id };
    double iT[3];
    #pragma unroll
    for (int j = 0; j < 3; j++)
        iT[j] = -((double)T[0] * iR[0 + j] + (double)T[1] * iR[3 + j]
                  + (double)T[2] * iR[6 + j]);

    #pragma unroll
    for (int k = 0; k < 9; k++) { g_R[m][k] = R[k]; g_iR[m][k] = (float)iR[k]; }
    #pragma unroll
    for (int k = 0; k < 3; k++) { g_T[m][k] = T[k]; g_iT[m][k] = (float)iT[k]; }
}

__device__ __forceinline__ float dot3_fma(float x0, float x1, float x2,
                                          float m0, float m1, float m2) {
    return fmaf(x2, m2, fmaf(x1, m1, __fmul_rn(x0, m0)));
}

__device__ __forceinline__ unsigned float_to_ord(float f) {
    unsigned u = __float_as_uint(f);
    return (u & 0x80000000u) ? ~u : (u | 0x80000000u);
}
__device__ __forceinline__ float ord_to_float(unsigned u) {
    return (u & 0x80000000u) ? __uint_as_float(u ^ 0x80000000u)
                             : __uint_as_float(~u);
}

// count of elements < u (lower_bound) / <= u (upper_bound) in sorted run
__device__ __forceinline__ int cnt_lt(const unsigned* a, int L, unsigned u) {
    int lo = 0, hi = L;
    while (lo < hi) { int mid = (lo + hi) >> 1; if (a[mid] <  u) lo = mid + 1; else hi = mid; }
    return lo;
}
__device__ __forceinline__ int cnt_le(const unsigned* a, int L, unsigned u) {
    int lo = 0, hi = L;
    while (lo < hi) { int mid = (lo + hi) >> 1; if (a[mid] <= u) lo = mid + 1; else hi = mid; }
    return lo;
}

// ---------------------------------------------------------------------------
// Fused kernel: one block (576 threads) per ray.
//   warps 0-1  : load the 64 pre-sorted base lengths
//   warps 2-17 : object m = warp-2, lane = sample s: full geometry (identical
//                fp ops to Round 7), write pts/dirs, then register-bitonic
//                sort of the 32-key run (ord(z)<<32 | s for stability)
//   then       : 17-way stable merge by ranking (binary searches), staged
//                coalesced writes of sorted lengths / nodes / mask.
// ---------------------------------------------------------------------------
__global__ void __launch_bounds__(TOTAL)
fused_kernel(const float* __restrict__ origins,
             const float* __restrict__ directions,
             const float* __restrict__ lengths,
             float* __restrict__ out_len,
             float* __restrict__ out_node,
             float* __restrict__ out_mask,
             float* __restrict__ out_pts,
             float* __restrict__ out_dirs) {
    __shared__ unsigned      s_vals[TOTAL];   // ord-keys, run-major, each run sorted
    __shared__ float         s_ov[TOTAL];     // staged sorted values
    __shared__ signed char   s_on[TOTAL];     // staged sorted node ids
    __shared__ unsigned char s_hit[N_OBJ];

    const int n    = blockIdx.x;
    const int tid  = threadIdx.x;
    const int wid  = tid >> 5;
    const int lane = tid & 31;

    if (wid < 2) {
        // base lengths: already sorted ascending (setup sorts them)
        s_vals[tid] = float_to_ord(__ldg(lengths + (size_t)n * N_BASE + tid));
    } else {
        const int m = wid - 2;

        float ox = __ldg(origins + 3 * n + 0);
        float oy = __ldg(origins + 3 * n + 1);
        float oz = __ldg(origins + 3 * n + 2);
        float dx = __ldg(directions + 3 * n + 0);
        float dy = __ldg(directions + 3 * n + 1);
        float dz = __ldg(directions + 3 * n + 2);

        float dss = __fadd_rn(__fadd_rn(__fmul_rn(dx, dx), __fmul_rn(dy, dy)),
                              __fmul_rn(dz, dz));
        float drs = rsqrt_approx(dss);
        float dwx = __fmul_rn(dx, drs), dwy = __fmul_rn(dy, drs), dwz = __fmul_rn(dz, drs);

        const float* R = g_R[m];
        const float* T = g_T[m];
        float oo0 = __fadd_rn(dot3_fma(ox, oy, oz, R[0], R[3], R[6]), T[0]);
        float oo1 = __fadd_rn(dot3_fma(ox, oy, oz, R[1], R[4], R[7]), T[1]);
        float oo2 = __fadd_rn(dot3_fma(ox, oy, oz, R[2], R[5], R[8]), T[2]);
        float dr0 = dot3_fma(dwx, dwy, dwz, R[0], R[3], R[6]);
        float dr1 = dot3_fma(dwx, dwy, dwz, R[1], R[4], R[7]);
        float dr2 = dot3_fma(dwx, dwy, dwz, R[2], R[5], R[8]);
        float oss = __fadd_rn(__fadd_rn(__fmul_rn(dr0, dr0), __fmul_rn(dr1, dr1)),
                              __fmul_rn(dr2, dr2));
        float ors = rsqrt_approx(oss);
        float do0 = __fmul_rn(dr0, ors), do1 = __fmul_rn(dr1, ors), do2 = __fmul_rn(dr2, ors);

        float i0 = __fdiv_rn(1.f, do0), i1 = __fdiv_rn(1.f, do1), i2 = __fdiv_rn(1.f, do2);
        float t0x = __fmul_rn(__fsub_rn(-1.f, oo0), i0), t1x = __fmul_rn(__fsub_rn(1.f, oo0), i0);
        float t0y = __fmul_rn(__fsub_rn(-1.f, oo1), i1), t1y = __fmul_rn(__fsub_rn(1.f, oo1), i1);
        float t0z = __fmul_rn(__fsub_rn(-1.f, oo2), i2), t1z = __fmul_rn(__fsub_rn(1.f, oo2), i2);
        float tmin = fmaxf(fmaxf(fminf(t0x, t1x), fminf(t0y, t1y)), fminf(t0z, t1z));
        float tmax = fminf(fminf(fmaxf(t0x, t1x), fmaxf(t0y, t1y)), fmaxf(t0z, t1z));
        bool hit = (tmax > tmin) && (tmax > 0.f);
        float tin = fmaxf(tmin, 0.f);
        float hf  = hit ? 1.f : 0.f;

        float lin = __fdiv_rn((float)lane, 31.0f);
        float zo  = __fadd_rn(tin, __fmul_rn(__fsub_rn(tmax, tin), lin));
        float p0 = __fadd_rn(oo0, __fmul_rn(do0, zo));
        float p1 = __fadd_rn(oo1, __fmul_rn(do1, zo));
        float p2 = __fadd_rn(oo2, __fmul_rn(do2, zo));

        size_t base = ((size_t)(m * N_RAYS + n) * N_SAMPLES + lane) * 3;
        out_pts [base + 0] = __fmul_rn(p0, hf);
        out_pts [base + 1] = __fmul_rn(p1, hf);
        out_pts [base + 2] = __fmul_rn(p2, hf);
        out_dirs[base + 0] = __fmul_rn(do0, hf);
        out_dirs[base + 1] = __fmul_rn(do1, hf);
        out_dirs[base + 2] = __fmul_rn(do2, hf);

        const float* iR = g_iR[m];
        const float* iT = g_iT[m];
        float w0 = __fadd_rn(dot3_fma(p0, p1, p2, iR[0], iR[3], iR[6]), iT[0]);
        float w1 = __fadd_rn(dot3_fma(p0, p1, p2, iR[1], iR[4], iR[7]), iT[1]);
        float w2 = __fadd_rn(dot3_fma(p0, p1, p2, iR[2], iR[5], iR[8]), iT[2]);
        float q0 = __fsub_rn(w0, ox), q1 = __fsub_rn(w1, oy), q2 = __fsub_rn(w2, oz);
        float zw = dot3_fma(q0, q1, q2, dwx, dwy, dwz);

        float v = hit ? zw : MISS;
        if (lane == 0) s_hit[m] = hit ? 1 : 0;

        // register bitonic sort of the 32-key run (stable via |s tie-break)
        unsigned long long key =
            ((unsigned long long)float_to_ord(v) << 32) | (unsigned)lane;
        #pragma unroll
        for (int k = 2; k <= 32; k <<= 1) {
            #pragma unroll
            for (int j = k >> 1; j > 0; j >>= 1) {
                unsigned long long other = __shfl_xor_sync(0xffffffffu, key, j);
                bool low = (lane & j) == 0;
                bool asc = (lane & k) == 0;
                unsigned long long mn = key < other ? key : other;
                unsigned long long mx = key < other ? other : key;
                key = (low == asc) ? mn : mx;
            }
        }
        s_vals[tid] = (unsigned)(key >> 32);
    }
    __syncthreads();

    // ---- stable 17-way merge by ranking ----
    {
        unsigned u = s_vals[tid];
        int r = (tid < N_BASE) ? 0 : (1 + ((tid - N_BASE) >> 5));
        int runStart = (r == 0) ? 0 : N_BASE + ((r - 1) << 5);
        int rank = tid - runStart;   // elements of own run before me

        // base run (r'=0)
        if (r != 0) rank += cnt_le(s_vals, N_BASE, u);
        // object runs
        #pragma unroll 4
        for (int rr = 1; rr <= N_OBJ; rr++) {
            if (rr == r) continue;
            const unsigned* a = s_vals + N_BASE + ((rr - 1) << 5);
            rank += (rr < r) ? cnt_le(a, N_SAMPLES, u) : cnt_lt(a, N_SAMPLES, u);
        }

        int node = -1;
        if (r > 0 && s_hit[r - 1]) node = r - 1;
        s_ov[rank] = ord_to_float(u);
        s_on[rank] = (signed char)node;
    }
    __syncthreads();

    // ---- coalesced output ----
    {
        size_t ob = (size_t)n * TOTAL + tid;
        float v = s_ov[tid];
        int nd = (int)s_on[tid];
        out_len [ob] = v;
        out_node[ob] = (float)nd;
        out_mask[ob] = (nd >= 0) ? 1.f : 0.f;
    }
}

// ---------------------------------------------------------------------------
extern "C" void kernel_launch(void* const* d_in, const int* in_sizes, int n_in,
                              void* d_out, int out_size) {
    const float* origins    = (const float*)d_in[0];
    const float* directions = (const float*)d_in[1];
    const float* lengths    = (const float*)d_in[2];
    const float* trafos     = (const float*)d_in[3];
    // d_in[4] = rots_w2o unused (composed linear part identical to trafos@scales)
    const float* scales     = (const float*)d_in[5];

    float* out = (float*)d_out;
    size_t nc = (size_t)N_RAYS * TOTAL;
    float* o_len  = out;
    float* o_node = out + nc;
    float* o_mask = out + 2 * nc;
    float* o_pts  = out + 3 * nc;
    float* o_dirs = o_pts + (size_t)N_OBJ * N_RAYS * N_SAMPLES * 3;

    precompute_kernel<<<1, 32>>>(trafos, scales);
    fused_kernel<<<N_RAYS, TOTAL>>>(origins, directions, lengths,
                                    o_len, o_node, o_mask, o_pts, o_dirs);
}

// round 9
// speedup vs baseline: 2.0545x; 1.3448x over previous
#include <cuda_runtime.h>
#include <stdint.h>

#define N_RAYS    32768
#define N_OBJ     16
#define N_SAMPLES 32
#define N_BASE    64
#define TOTAL     (N_BASE + N_OBJ * N_SAMPLES)   // 576
#define MISS      1e10f

// ---- per-object transform constants ----
__device__ float g_R [N_OBJ][9];
__device__ float g_T [N_OBJ][3];
__device__ float g_iR[N_OBJ][9];
__device__ float g_iT[N_OBJ][3];

// XLA-GPU lowers x/sqrt(s) -> x * rsqrt(s) with rsqrt.approx.f32.
__device__ __forceinline__ float rsqrt_approx(float x) {
    float r;
    asm("rsqrt.approx.f32 %0, %1;" : "=f"(r) : "f"(x));
    return r;
}

// ---------------------------------------------------------------------------
// Kernel 0: pt_mat = trafos @ scales; inverse exact in fp64, rounded to fp32.
// (bit-identical to Round 7 — arithmetic locked)
// ---------------------------------------------------------------------------
__global__ void precompute_kernel(const float* __restrict__ trafos,
                                  const float* __restrict__ scales) {
    int m = threadIdx.x;
    if (m >= N_OBJ) return;
    const float* A = trafos + m * 16;
    const float* B = scales + m * 16;
    float s0 = B[0], s1 = B[5], s2 = B[10];
    float R[9], T[3];
    #pragma unroll
    for (int i = 0; i < 3; i++) {
        R[i * 3 + 0] = __fmul_rn(A[i * 4 + 0], s0);
        R[i * 3 + 1] = __fmul_rn(A[i * 4 + 1], s1);
        R[i * 3 + 2] = __fmul_rn(A[i * 4 + 2], s2);
    }
    T[0] = __fmul_rn(A[12], s0);
    T[1] = __fmul_rn(A[13], s1);
    T[2] = __fmul_rn(A[14], s2);

    double a = R[0], b = R[1], c = R[2];
    double d = R[3], e = R[4], f = R[5];
    double g = R[6], h = R[7], i = R[8];
    double A0 = e * i - f * h, B0 = -(d * i - f * g), C0 = d * h - e * g;
    double D0 = -(b * i - c * h), E0 = a * i - c * g, F0 = -(a * h - b * g);
    double G0 = b * f - c * e, H0 = -(a * f - c * d), I0 = a * e - b * d;
    double det = a * A0 + b * B0 + c * C0;
    double id = 1.0 / det;
    double iR[9] = { A0 * id, D0 * id, G0 * id,
                     B0 * id, E0 * id, H0 * id,
                     C0 * id, F0 * id, I0 * id };
    double iT[3];
    #pragma unroll
    for (int j = 0; j < 3; j++)
        iT[j] = -((double)T[0] * iR[0 + j] + (double)T[1] * iR[3 + j]
                  + (double)T[2] * iR[6 + j]);

    #pragma unroll
    for (int k = 0; k < 9; k++) { g_R[m][k] = R[k]; g_iR[m][k] = (float)iR[k]; }
    #pragma unroll
    for (int k = 0; k < 3; k++) { g_T[m][k] = T[k]; g_iT[m][k] = (float)iT[k]; }
}

__device__ __forceinline__ float dot3_fma(float x0, float x1, float x2,
                                          float m0, float m1, float m2) {
    return fmaf(x2, m2, fmaf(x1, m1, __fmul_rn(x0, m0)));
}

__device__ __forceinline__ unsigned float_to_ord(float f) {
    unsigned u = __float_as_uint(f);
    return (u & 0x80000000u) ? ~u : (u | 0x80000000u);
}
__device__ __forceinline__ float ord_to_float(unsigned u) {
    return (u & 0x80000000u) ? __uint_as_float(u ^ 0x80000000u)
                             : __uint_as_float(~u);
}

// lower_bound over unique 64-bit keys
__device__ __forceinline__ int lower_bound64(const unsigned long long* a, int L,
                                             unsigned long long u) {
    int lo = 0, hi = L;
    while (lo < hi) {
        int mid = (lo + hi) >> 1;
        if (a[mid] < u) lo = mid + 1; else hi = mid;
    }
    return lo;
}

// one merge round over the 512 object slots [64,576): runs of length HALF ->
// runs of length 2*HALF. tid<64 copies the base run through.
template <int HALF>
__device__ __forceinline__ void merge_stage(const unsigned long long* __restrict__ src,
                                            unsigned long long* __restrict__ dst,
                                            int tid) {
    unsigned long long key = src[tid];
    if (tid < N_BASE) { dst[tid] = key; return; }
    int idx = tid - N_BASE;                       // 0..511
    int pairBase = idx & ~(2 * HALF - 1);
    int r = idx & (2 * HALF - 1);
    const unsigned long long* p = src + N_BASE + pairBase;
    int newpos;
    if (r < HALF) newpos = r + lower_bound64(p + HALF, HALF, key);
    else          newpos = (r - HALF) + lower_bound64(p, HALF, key);
    dst[N_BASE + pairBase + newpos] = key;
}

// ---------------------------------------------------------------------------
// Fused kernel: one block (576 threads) per ray.
// Geometry identical to R8. Sort: per-warp register bitonic (object runs),
// then a pairwise stable merge tree (5 rounds) on keys ord<<32|origidx.
// ---------------------------------------------------------------------------
__global__ void __launch_bounds__(TOTAL)
fused_kernel(const float* __restrict__ origins,
             const float* __restrict__ directions,
             const float* __restrict__ lengths,
             float* __restrict__ out_len,
             float* __restrict__ out_node,
             float* __restrict__ out_mask,
             float* __restrict__ out_pts,
             float* __restrict__ out_dirs) {
    __shared__ unsigned long long bufA[TOTAL];
    __shared__ unsigned long long bufB[TOTAL];
    __shared__ unsigned char s_hit[N_OBJ];

    const int n    = blockIdx.x;
    const int tid  = threadIdx.x;
    const int wid  = tid >> 5;
    const int lane = tid & 31;

    if (wid < 2) {
        // base lengths: pre-sorted ascending; key = ord<<32 | origidx(=tid)
        float f = __ldg(lengths + (size_t)n * N_BASE + tid);
        bufA[tid] = ((unsigned long long)float_to_ord(f) << 32) | (unsigned)tid;
    } else {
        const int m = wid - 2;

        float ox = __ldg(origins + 3 * n + 0);
        float oy = __ldg(origins + 3 * n + 1);
        float oz = __ldg(origins + 3 * n + 2);
        float dx = __ldg(directions + 3 * n + 0);
        float dy = __ldg(directions + 3 * n + 1);
        float dz = __ldg(directions + 3 * n + 2);

        float dss = __fadd_rn(__fadd_rn(__fmul_rn(dx, dx), __fmul_rn(dy, dy)),
                              __fmul_rn(dz, dz));
        float drs = rsqrt_approx(dss);
        float dwx = __fmul_rn(dx, drs), dwy = __fmul_rn(dy, drs), dwz = __fmul_rn(dz, drs);

        const float* R = g_R[m];
        const float* T = g_T[m];
        float oo0 = __fadd_rn(dot3_fma(ox, oy, oz, R[0], R[3], R[6]), T[0]);
        float oo1 = __fadd_rn(dot3_fma(ox, oy, oz, R[1], R[4], R[7]), T[1]);
        float oo2 = __fadd_rn(dot3_fma(ox, oy, oz, R[2], R[5], R[8]), T[2]);
        float dr0 = dot3_fma(dwx, dwy, dwz, R[0], R[3], R[6]);
        float dr1 = dot3_fma(dwx, dwy, dwz, R[1], R[4], R[7]);
        float dr2 = dot3_fma(dwx, dwy, dwz, R[2], R[5], R[8]);
        float oss = __fadd_rn(__fadd_rn(__fmul_rn(dr0, dr0), __fmul_rn(dr1, dr1)),
                              __fmul_rn(dr2, dr2));
        float ors = rsqrt_approx(oss);
        float do0 = __fmul_rn(dr0, ors), do1 = __fmul_rn(dr1, ors), do2 = __fmul_rn(dr2, ors);

        float i0 = __fdiv_rn(1.f, do0), i1 = __fdiv_rn(1.f, do1), i2 = __fdiv_rn(1.f, do2);
        float t0x = __fmul_rn(__fsub_rn(-1.f, oo0), i0), t1x = __fmul_rn(__fsub_rn(1.f, oo0), i0);
        float t0y = __fmul_rn(__fsub_rn(-1.f, oo1), i1), t1y = __fmul_rn(__fsub_rn(1.f, oo1), i1);
        float t0z = __fmul_rn(__fsub_rn(-1.f, oo2), i2), t1z = __fmul_rn(__fsub_rn(1.f, oo2), i2);
        float tmin = fmaxf(fmaxf(fminf(t0x, t1x), fminf(t0y, t1y)), fminf(t0z, t1z));
        float tmax = fminf(fminf(fmaxf(t0x, t1x), fmaxf(t0y, t1y)), fmaxf(t0z, t1z));
        bool hit = (tmax > tmin) && (tmax > 0.f);
        float tin = fmaxf(tmin, 0.f);
        float hf  = hit ? 1.f : 0.f;

        float lin = __fdiv_rn((float)lane, 31.0f);
        float zo  = __fadd_rn(tin, __fmul_rn(__fsub_rn(tmax, tin), lin));
        float p0 = __fadd_rn(oo0, __fmul_rn(do0, zo));
        float p1 = __fadd_rn(oo1, __fmul_rn(do1, zo));
        float p2 = __fadd_rn(oo2, __fmul_rn(do2, zo));

        size_t base = ((size_t)(m * N_RAYS + n) * N_SAMPLES + lane) * 3;
        out_pts [base + 0] = __fmul_rn(p0, hf);
        out_pts [base + 1] = __fmul_rn(p1, hf);
        out_pts [base + 2] = __fmul_rn(p2, hf);
        out_dirs[base + 0] = __fmul_rn(do0, hf);
        out_dirs[base + 1] = __fmul_rn(do1, hf);
        out_dirs[base + 2] = __fmul_rn(do2, hf);

        const float* iR = g_iR[m];
        const float* iT = g_iT[m];
        float w0 = __fadd_rn(dot3_fma(p0, p1, p2, iR[0], iR[3], iR[6]), iT[0]);
        float w1 = __fadd_rn(dot3_fma(p0, p1, p2, iR[1], iR[4], iR[7]), iT[1]);
        float w2 = __fadd_rn(dot3_fma(p0, p1, p2, iR[2], iR[5], iR[8]), iT[2]);
        float q0 = __fsub_rn(w0, ox), q1 = __fsub_rn(w1, oy), q2 = __fsub_rn(w2, oz);
        float zw = dot3_fma(q0, q1, q2, dwx, dwy, dwz);

        float v = hit ? zw : MISS;
        if (lane == 0) s_hit[m] = hit ? 1 : 0;

        // register bitonic sort of the 32-key run; tie-break by s keeps
        // stability, and s rides in the low bits for index reconstruction.
        unsigned long long key =
            ((unsigned long long)float_to_ord(v) << 32) | (unsigned)lane;
        #pragma unroll
        for (int k = 2; k <= 32; k <<= 1) {
            #pragma unroll
            for (int j = k >> 1; j > 0; j >>= 1) {
                unsigned long long other = __shfl_xor_sync(0xffffffffu, key, j);
                bool low = (lane & j) == 0;
                bool asc = (lane & k) == 0;
                unsigned long long mn = key < other ? key : other;
                unsigned long long mx = key < other ? other : key;
                key = (low == asc) ? mn : mx;
            }
        }
        // promote low bits to the global original index: 64 + 32*m + s
        unsigned s = (unsigned)key & 31u;
        bufA[tid] = (key & 0xFFFFFFFF00000000ull)
                  | (unsigned long long)(N_BASE + (m << 5) + s);
    }
    __syncthreads();

    // ---- pairwise stable merge tree (unique keys => lower_bound only) ----
    merge_stage<32 >(bufA, bufB, tid); __syncthreads();
    merge_stage<64 >(bufB, bufA, tid); __syncthreads();
    merge_stage<128>(bufA, bufB, tid); __syncthreads();
    merge_stage<256>(bufB, bufA, tid); __syncthreads();

    // final: merge base run [0,64) with object run [64,576)
    {
        unsigned long long key = bufA[tid];
        int newpos;
        if (tid < N_BASE) newpos = tid + lower_bound64(bufA + N_BASE, TOTAL - N_BASE, key);
        else              newpos = (tid - N_BASE) + lower_bound64(bufA, N_BASE, key);
        bufB[newpos] = key;
    }
    __syncthreads();

    // ---- coalesced output ----
    {
        unsigned long long key = bufB[tid];
        unsigned idx = (unsigned)key & 0x3FFu;
        float v = ord_to_float((unsigned)(key >> 32));
        int node = -1;
        if (idx >= N_BASE) {
            int m = (int)((idx - N_BASE) >> 5);
            if (s_hit[m]) node = m;
        }
        size_t ob = (size_t)n * TOTAL + tid;
        out_len [ob] = v;
        out_node[ob] = (float)node;
        out_mask[ob] = (node >= 0) ? 1.f : 0.f;
    }
}

// ---------------------------------------------------------------------------
extern "C" void kernel_launch(void* const* d_in, const int* in_sizes, int n_in,
                              void* d_out, int out_size) {
    const float* origins    = (const float*)d_in[0];
    const float* directions = (const float*)d_in[1];
    const float* lengths    = (const float*)d_in[2];
    const float* trafos     = (const float*)d_in[3];
    // d_in[4] = rots_w2o unused (composed linear part identical to trafos@scales)
    const float* scales     = (const float*)d_in[5];

    float* out = (float*)d_out;
    size_t nc = (size_t)N_RAYS * TOTAL;
    float* o_len  = out;
    float* o_node = out + nc;
    float* o_mask = out + 2 * nc;
    float* o_pts  = out + 3 * nc;
    float* o_dirs = o_pts + (size_t)N_OBJ * N_RAYS * N_SAMPLES * 3;

    precompute_kernel<<<1, 32>>>(trafos, scales);
    fused_kernel<<<N_RAYS, TOTAL>>>(origins, directions, lengths,
                                    o_len, o_node, o_mask, o_pts, o_dirs);
}

// round 10
// speedup vs baseline: 2.7856x; 1.3559x over previous
#include <cuda_runtime.h>
#include <stdint.h>

#define N_RAYS    32768
#define N_OBJ     16
#define N_SAMPLES 32
#define N_BASE    64
#define TOTAL     (N_BASE + N_OBJ * N_SAMPLES)   // 576
#define MISS      1e10f

// ---- per-object transform constants ----
__device__ float g_R [N_OBJ][9];
__device__ float g_T [N_OBJ][3];
__device__ float g_iR[N_OBJ][9];
__device__ float g_iT[N_OBJ][3];

// XLA-GPU lowers x/sqrt(s) -> x * rsqrt(s) with rsqrt.approx.f32.
__device__ __forceinline__ float rsqrt_approx(float x) {
    float r;
    asm("rsqrt.approx.f32 %0, %1;" : "=f"(r) : "f"(x));
    return r;
}

// ---------------------------------------------------------------------------
// Kernel 0: pt_mat = trafos @ scales; inverse exact in fp64, rounded to fp32.
// (bit-identical to Round 7 — arithmetic locked)
// ---------------------------------------------------------------------------
__global__ void precompute_kernel(const float* __restrict__ trafos,
                                  const float* __restrict__ scales) {
    int m = threadIdx.x;
    if (m >= N_OBJ) return;
    const float* A = trafos + m * 16;
    const float* B = scales + m * 16;
    float s0 = B[0], s1 = B[5], s2 = B[10];
    float R[9], T[3];
    #pragma unroll
    for (int i = 0; i < 3; i++) {
        R[i * 3 + 0] = __fmul_rn(A[i * 4 + 0], s0);
        R[i * 3 + 1] = __fmul_rn(A[i * 4 + 1], s1);
        R[i * 3 + 2] = __fmul_rn(A[i * 4 + 2], s2);
    }
    T[0] = __fmul_rn(A[12], s0);
    T[1] = __fmul_rn(A[13], s1);
    T[2] = __fmul_rn(A[14], s2);

    double a = R[0], b = R[1], c = R[2];
    double d = R[3], e = R[4], f = R[5];
    double g = R[6], h = R[7], i = R[8];
    double A0 = e * i - f * h, B0 = -(d * i - f * g), C0 = d * h - e * g;
    double D0 = -(b * i - c * h), E0 = a * i - c * g, F0 = -(a * h - b * g);
    double G0 = b * f - c * e, H0 = -(a * f - c * d), I0 = a * e - b * d;
    double det = a * A0 + b * B0 + c * C0;
    double id = 1.0 / det;
    double iR[9] = { A0 * id, D0 * id, G0 * id,
                     B0 * id, E0 * id, H0 * id,
                     C0 * id, F0 * id, I0 * id };
    double iT[3];
    #pragma unroll
    for (int j = 0; j < 3; j++)
        iT[j] = -((double)T[0] * iR[0 + j] + (double)T[1] * iR[3 + j]
                  + (double)T[2] * iR[6 + j]);

    #pragma unroll
    for (int k = 0; k < 9; k++) { g_R[m][k] = R[k]; g_iR[m][k] = (float)iR[k]; }
    #pragma unroll
    for (int k = 0; k < 3; k++) { g_T[m][k] = T[k]; g_iT[m][k] = (float)iT[k]; }
}

__device__ __forceinline__ float dot3_fma(float x0, float x1, float x2,
                                          float m0, float m1, float m2) {
    return fmaf(x2, m2, fmaf(x1, m1, __fmul_rn(x0, m0)));
}

__device__ __forceinline__ unsigned float_to_ord(float f) {
    unsigned u = __float_as_uint(f);
    return (u & 0x80000000u) ? ~u : (u | 0x80000000u);
}
__device__ __forceinline__ float ord_to_float(unsigned u) {
    return (u & 0x80000000u) ? __uint_as_float(u ^ 0x80000000u)
                             : __uint_as_float(~u);
}

// Branchless lower_bound over a power-of-two-length sorted run of unique keys.
// log2(L) predicated steps + 1 final adjust; reads stay in [0, L-1].
template <int L>
__device__ __forceinline__ int lbp2(const unsigned long long* __restrict__ a,
                                    unsigned long long u) {
    int base = 0;
    #pragma unroll
    for (int half = L >> 1; half > 0; half >>= 1)
        base += (a[base + half - 1] < u) ? half : 0;
    return base + ((a[base] < u) ? 1 : 0);
}

// one merge round over the 512 object slots [64,576): runs of length HALF ->
// runs of length 2*HALF. tid<64 copies the base run through.
template <int HALF>
__device__ __forceinline__ void merge_stage(const unsigned long long* __restrict__ src,
                                            unsigned long long* __restrict__ dst,
                                            int tid) {
    unsigned long long key = src[tid];
    if (tid < N_BASE) { dst[tid] = key; return; }
    int idx = tid - N_BASE;                       // 0..511
    int pairBase = idx & ~(2 * HALF - 1);
    int r = idx & (2 * HALF - 1);
    const unsigned long long* p = src + N_BASE + pairBase;
    int newpos;
    if (r < HALF) newpos = r + lbp2<HALF>(p + HALF, key);
    else          newpos = (r - HALF) + lbp2<HALF>(p, key);
    dst[N_BASE + pairBase + newpos] = key;
}

// ---------------------------------------------------------------------------
// Fused kernel: one block (576 threads) per ray. Geometry identical to R8/R9.
// Sort: per-warp register bitonic, then pairwise stable merge tree (5 rounds)
// with branchless power-of-2 searches. 3 blocks/SM forced for occupancy.
// ---------------------------------------------------------------------------
__global__ void __launch_bounds__(TOTAL, 3)
fused_kernel(const float* __restrict__ origins,
             const float* __restrict__ directions,
             const float* __restrict__ lengths,
             float* __restrict__ out_len,
             float* __restrict__ out_node,
             float* __restrict__ out_mask,
             float* __restrict__ out_pts,
             float* __restrict__ out_dirs) {
    __shared__ unsigned long long bufA[TOTAL];
    __shared__ unsigned long long bufB[TOTAL];
    __shared__ unsigned char s_hit[N_OBJ];

    const int n    = blockIdx.x;
    const int tid  = threadIdx.x;
    const int wid  = tid >> 5;
    const int lane = tid & 31;

    if (wid < 2) {
        // base lengths: pre-sorted ascending; key = ord<<32 | origidx(=tid)
        float f = __ldg(lengths + (size_t)n * N_BASE + tid);
        bufA[tid] = ((unsigned long long)float_to_ord(f) << 32) | (unsigned)tid;
    } else {
        const int m = wid - 2;

        float ox = __ldg(origins + 3 * n + 0);
        float oy = __ldg(origins + 3 * n + 1);
        float oz = __ldg(origins + 3 * n + 2);
        float dx = __ldg(directions + 3 * n + 0);
        float dy = __ldg(directions + 3 * n + 1);
        float dz = __ldg(directions + 3 * n + 2);

        float dss = __fadd_rn(__fadd_rn(__fmul_rn(dx, dx), __fmul_rn(dy, dy)),
                              __fmul_rn(dz, dz));
        float drs = rsqrt_approx(dss);
        float dwx = __fmul_rn(dx, drs), dwy = __fmul_rn(dy, drs), dwz = __fmul_rn(dz, drs);

        const float* R = g_R[m];
        const float* T = g_T[m];
        float oo0 = __fadd_rn(dot3_fma(ox, oy, oz, R[0], R[3], R[6]), T[0]);
        float oo1 = __fadd_rn(dot3_fma(ox, oy, oz, R[1], R[4], R[7]), T[1]);
        float oo2 = __fadd_rn(dot3_fma(ox, oy, oz, R[2], R[5], R[8]), T[2]);
        float dr0 = dot3_fma(dwx, dwy, dwz, R[0], R[3], R[6]);
        float dr1 = dot3_fma(dwx, dwy, dwz, R[1], R[4], R[7]);
        float dr2 = dot3_fma(dwx, dwy, dwz, R[2], R[5], R[8]);
        float oss = __fadd_rn(__fadd_rn(__fmul_rn(dr0, dr0), __fmul_rn(dr1, dr1)),
                              __fmul_rn(dr2, dr2));
        float ors = rsqrt_approx(oss);
        float do0 = __fmul_rn(dr0, ors), do1 = __fmul_rn(dr1, ors), do2 = __fmul_rn(dr2, ors);

        float i0 = __fdiv_rn(1.f, do0), i1 = __fdiv_rn(1.f, do1), i2 = __fdiv_rn(1.f, do2);
        float t0x = __fmul_rn(__fsub_rn(-1.f, oo0), i0), t1x = __fmul_rn(__fsub_rn(1.f, oo0), i0);
        float t0y = __fmul_rn(__fsub_rn(-1.f, oo1), i1), t1y = __fmul_rn(__fsub_rn(1.f, oo1), i1);
        float t0z = __fmul_rn(__fsub_rn(-1.f, oo2), i2), t1z = __fmul_rn(__fsub_rn(1.f, oo2), i2);
        float tmin = fmaxf(fmaxf(fminf(t0x, t1x), fminf(t0y, t1y)), fminf(t0z, t1z));
        float tmax = fminf(fminf(fmaxf(t0x, t1x), fmaxf(t0y, t1y)), fmaxf(t0z, t1z));
        bool hit = (tmax > tmin) && (tmax > 0.f);
        float tin = fmaxf(tmin, 0.f);
        float hf  = hit ? 1.f : 0.f;

        float lin = __fdiv_rn((float)lane, 31.0f);
        float zo  = __fadd_rn(tin, __fmul_rn(__fsub_rn(tmax, tin), lin));
        float p0 = __fadd_rn(oo0, __fmul_rn(do0, zo));
        float p1 = __fadd_rn(oo1, __fmul_rn(do1, zo));
        float p2 = __fadd_rn(oo2, __fmul_rn(do2, zo));

        size_t base = ((size_t)(m * N_RAYS + n) * N_SAMPLES + lane) * 3;
        out_pts [base + 0] = __fmul_rn(p0, hf);
        out_pts [base + 1] = __fmul_rn(p1, hf);
        out_pts [base + 2] = __fmul_rn(p2, hf);
        out_dirs[base + 0] = __fmul_rn(do0, hf);
        out_dirs[base + 1] = __fmul_rn(do1, hf);
        out_dirs[base + 2] = __fmul_rn(do2, hf);

        const float* iR = g_iR[m];
        const float* iT = g_iT[m];
        float w0 = __fadd_rn(dot3_fma(p0, p1, p2, iR[0], iR[3], iR[6]), iT[0]);
        float w1 = __fadd_rn(dot3_fma(p0, p1, p2, iR[1], iR[4], iR[7]), iT[1]);
        float w2 = __fadd_rn(dot3_fma(p0, p1, p2, iR[2], iR[5], iR[8]), iT[2]);
        float q0 = __fsub_rn(w0, ox), q1 = __fsub_rn(w1, oy), q2 = __fsub_rn(w2, oz);
        float zw = dot3_fma(q0, q1, q2, dwx, dwy, dwz);

        float v = hit ? zw : MISS;
        if (lane == 0) s_hit[m] = hit ? 1 : 0;

        // register bitonic sort of the 32-key run (stable via |s tie-break)
        unsigned long long key =
            ((unsigned long long)float_to_ord(v) << 32) | (unsigned)lane;
        #pragma unroll
        for (int k = 2; k <= 32; k <<= 1) {
            #pragma unroll
            for (int j = k >> 1; j > 0; j >>= 1) {
                unsigned long long other = __shfl_xor_sync(0xffffffffu, key, j);
                bool low = (lane & j) == 0;
                bool asc = (lane & k) == 0;
                unsigned long long mn = key < other ? key : other;
                unsigned long long mx = key < other ? other : key;
                key = (low == asc) ? mn : mx;
            }
        }
        // promote low bits to the global original index: 64 + 32*m + s
        unsigned s = (unsigned)key & 31u;
        bufA[tid] = (key & 0xFFFFFFFF00000000ull)
                  | (unsigned long long)(N_BASE + (m << 5) + s);
    }
    __syncthreads();

    // ---- pairwise stable merge tree (unique keys => plain lower_bound) ----
    merge_stage<32 >(bufA, bufB, tid); __syncthreads();
    merge_stage<64 >(bufB, bufA, tid); __syncthreads();
    merge_stage<128>(bufA, bufB, tid); __syncthreads();
    merge_stage<256>(bufB, bufA, tid); __syncthreads();

    // final: merge base run [0,64) with object run [64,576)
    {
        unsigned long long key = bufA[tid];
        int newpos;
        if (tid < N_BASE) newpos = tid + lbp2<512>(bufA + N_BASE, key);
        else              newpos = (tid - N_BASE) + lbp2<N_BASE>(bufA, key);
        bufB[newpos] = key;
    }
    __syncthreads();

    // ---- coalesced output ----
    {
        unsigned long long key = bufB[tid];
        unsigned idx = (unsigned)key & 0x3FFu;
        float v = ord_to_float((unsigned)(key >> 32));
        int node = -1;
        if (idx >= N_BASE) {
            int m = (int)((idx - N_BASE) >> 5);
            if (s_hit[m]) node = m;
        }
        size_t ob = (size_t)n * TOTAL + tid;
        out_len [ob] = v;
        out_node[ob] = (float)node;
        out_mask[ob] = (node >= 0) ? 1.f : 0.f;
    }
}

// ---------------------------------------------------------------------------
extern "C" void kernel_launch(void* const* d_in, const int* in_sizes, int n_in,
                              void* d_out, int out_size) {
    const float* origins    = (const float*)d_in[0];
    const float* directions = (const float*)d_in[1];
    const float* lengths    = (const float*)d_in[2];
    const float* trafos     = (const float*)d_in[3];
    // d_in[4] = rots_w2o unused (composed linear part identical to trafos@scales)
    const float* scales     = (const float*)d_in[5];

    float* out = (float*)d_out;
    size_t nc = (size_t)N_RAYS * TOTAL;
    float* o_len  = out;
    float* o_node = out + nc;
    float* o_mask = out + 2 * nc;
    float* o_pts  = out + 3 * nc;
    float* o_dirs = o_pts + (size_t)N_OBJ * N_RAYS * N_SAMPLES * 3;

    precompute_kernel<<<1, 32>>>(trafos, scales);
    fused_kernel<<<N_RAYS, TOTAL>>>(origins, directions, lengths,
                                    o_len, o_node, o_mask, o_pts, o_dirs);
}

// round 11
// speedup vs baseline: 3.4860x; 1.2514x over previous
#include <cuda_runtime.h>
#include <stdint.h>

#define N_RAYS    32768
#define N_OBJ     16
#define N_SAMPLES 32
#define N_BASE    64
#define N_ZOBJ    (N_OBJ * N_SAMPLES)            // 512
#define TOTAL     (N_BASE + N_ZOBJ)              // 576
#define MISS      1e10f

// ---- per-object transform constants ----
__device__ float g_R [N_OBJ][9];
__device__ float g_T [N_OBJ][3];
__device__ float g_iR[N_OBJ][9];
__device__ float g_iT[N_OBJ][3];

// XLA-GPU lowers x/sqrt(s) -> x * rsqrt(s) with rsqrt.approx.f32.
__device__ __forceinline__ float rsqrt_approx(float x) {
    float r;
    asm("rsqrt.approx.f32 %0, %1;" : "=f"(r) : "f"(x));
    return r;
}

// ---------------------------------------------------------------------------
// Kernel 0: pt_mat = trafos @ scales; inverse exact in fp64, rounded to fp32.
// (bit-identical to Round 7 — arithmetic locked)
// ---------------------------------------------------------------------------
__global__ void precompute_kernel(const float* __restrict__ trafos,
                                  const float* __restrict__ scales) {
    int m = threadIdx.x;
    if (m >= N_OBJ) return;
    const float* A = trafos + m * 16;
    const float* B = scales + m * 16;
    float s0 = B[0], s1 = B[5], s2 = B[10];
    float R[9], T[3];
    #pragma unroll
    for (int i = 0; i < 3; i++) {
        R[i * 3 + 0] = __fmul_rn(A[i * 4 + 0], s0);
        R[i * 3 + 1] = __fmul_rn(A[i * 4 + 1], s1);
        R[i * 3 + 2] = __fmul_rn(A[i * 4 + 2], s2);
    }
    T[0] = __fmul_rn(A[12], s0);
    T[1] = __fmul_rn(A[13], s1);
    T[2] = __fmul_rn(A[14], s2);

    double a = R[0], b = R[1], c = R[2];
    double d = R[3], e = R[4], f = R[5];
    double g = R[6], h = R[7], i = R[8];
    double A0 = e * i - f * h, B0 = -(d * i - f * g), C0 = d * h - e * g;
    double D0 = -(b * i - c * h), E0 = a * i - c * g, F0 = -(a * h - b * g);
    double G0 = b * f - c * e, H0 = -(a * f - c * d), I0 = a * e - b * d;
    double det = a * A0 + b * B0 + c * C0;
    double id = 1.0 / det;
    double iR[9] = { A0 * id, D0 * id, G0 * id,
                     B0 * id, E0 * id, H0 * id,
                     C0 * id, F0 * id, I0 * id };
    double iT[3];
    #pragma unroll
    for (int j = 0; j < 3; j++)
        iT[j] = -((double)T[0] * iR[0 + j] + (double)T[1] * iR[3 + j]
                  + (double)T[2] * iR[6 + j]);

    #pragma unroll
    for (int k = 0; k < 9; k++) { g_R[m][k] = R[k]; g_iR[m][k] = (float)iR[k]; }
    #pragma unroll
    for (int k = 0; k < 3; k++) { g_T[m][k] = T[k]; g_iT[m][k] = (float)iT[k]; }
}

__device__ __forceinline__ float dot3_fma(float x0, float x1, float x2,
                                          float m0, float m1, float m2) {
    return fmaf(x2, m2, fmaf(x1, m1, __fmul_rn(x0, m0)));
}

__device__ __forceinline__ unsigned float_to_ord(float f) {
    unsigned u = __float_as_uint(f);
    return (u & 0x80000000u) ? ~u : (u | 0x80000000u);
}
__device__ __forceinline__ float ord_to_float(unsigned u) {
    return (u & 0x80000000u) ? __uint_as_float(u ^ 0x80000000u)
                             : __uint_as_float(~u);
}

// Branchless counts over power-of-two-length sorted arrays (32-bit keys).
template <int L>
__device__ __forceinline__ int cnt_lt32(const unsigned* __restrict__ a, unsigned u) {
    int base = 0;
    #pragma unroll
    for (int half = L >> 1; half > 0; half >>= 1)
        if (a[base + half - 1] < u) base += half;
    return base + ((a[base] < u) ? 1 : 0);
}
template <int L>
__device__ __forceinline__ int cnt_le32(const unsigned* __restrict__ a, unsigned u) {
    int base = 0;
    #pragma unroll
    for (int half = L >> 1; half > 0; half >>= 1)
        if (a[base + half - 1] <= u) base += half;
    return base + ((a[base] <= u) ? 1 : 0);
}

// One merge round: runs of length 2^LOG2H -> 2^(LOG2H+1). Thread carries its
// key in a register; only the 4-byte ord moves through smem. Left run uses
// cnt_lt of right (left's original indices are smaller), right uses cnt_le.
template <int LOG2H>
__device__ __forceinline__ int merge_round(const unsigned* __restrict__ src,
                                           unsigned* __restrict__ dst,
                                           int gpos, unsigned ord) {
    constexpr int HALF = 1 << LOG2H;
    int rank = gpos & (HALF - 1);
    int run  = gpos >> LOG2H;
    const unsigned* other = src + ((run ^ 1) << LOG2H);
    int cnt = (run & 1) ? cnt_le32<HALF>(other, ord)
                        : cnt_lt32<HALF>(other, ord);
    int np = ((run >> 1) << (LOG2H + 1)) + rank + cnt;
    dst[np] = ord;
    return np;
}

// ---------------------------------------------------------------------------
// Fused kernel: one block (576 threads) per ray. Geometry identical to R10.
// Sort: 32-bit per-warp bitonic, then payload-free 32-bit merge tree.
// ---------------------------------------------------------------------------
__global__ void __launch_bounds__(TOTAL, 3)
fused_kernel(const float* __restrict__ origins,
             const float* __restrict__ directions,
             const float* __restrict__ lengths,
             float* __restrict__ out_len,
             float* __restrict__ out_node,
             float* __restrict__ out_mask,
             float* __restrict__ out_pts,
             float* __restrict__ out_dirs) {
    __shared__ unsigned    s_objA[N_ZOBJ];
    __shared__ unsigned    s_objB[N_ZOBJ];
    __shared__ unsigned    s_base[N_BASE];
    __shared__ float       s_ov[TOTAL];
    __shared__ signed char s_on[TOTAL];

    const int n    = blockIdx.x;
    const int tid  = threadIdx.x;
    const int wid  = tid >> 5;
    const int lane = tid & 31;

    unsigned myord;
    int gpos = 0;
    int mynode = -1;

    if (wid < 2) {
        // base lengths: pre-sorted ascending; written once, never moved
        float f = __ldg(lengths + (size_t)n * N_BASE + tid);
        myord = float_to_ord(f);
        s_base[tid] = myord;
    } else {
        const int m = wid - 2;

        float ox = __ldg(origins + 3 * n + 0);
        float oy = __ldg(origins + 3 * n + 1);
        float oz = __ldg(origins + 3 * n + 2);
        float dx = __ldg(directions + 3 * n + 0);
        float dy = __ldg(directions + 3 * n + 1);
        float dz = __ldg(directions + 3 * n + 2);

        float dss = __fadd_rn(__fadd_rn(__fmul_rn(dx, dx), __fmul_rn(dy, dy)),
                              __fmul_rn(dz, dz));
        float drs = rsqrt_approx(dss);
        float dwx = __fmul_rn(dx, drs), dwy = __fmul_rn(dy, drs), dwz = __fmul_rn(dz, drs);

        const float* R = g_R[m];
        const float* T = g_T[m];
        float oo0 = __fadd_rn(dot3_fma(ox, oy, oz, R[0], R[3], R[6]), T[0]);
        float oo1 = __fadd_rn(dot3_fma(ox, oy, oz, R[1], R[4], R[7]), T[1]);
        float oo2 = __fadd_rn(dot3_fma(ox, oy, oz, R[2], R[5], R[8]), T[2]);
        float dr0 = dot3_fma(dwx, dwy, dwz, R[0], R[3], R[6]);
        float dr1 = dot3_fma(dwx, dwy, dwz, R[1], R[4], R[7]);
        float dr2 = dot3_fma(dwx, dwy, dwz, R[2], R[5], R[8]);
        float oss = __fadd_rn(__fadd_rn(__fmul_rn(dr0, dr0), __fmul_rn(dr1, dr1)),
                              __fmul_rn(dr2, dr2));
        float ors = rsqrt_approx(oss);
        float do0 = __fmul_rn(dr0, ors), do1 = __fmul_rn(dr1, ors), do2 = __fmul_rn(dr2, ors);

        float i0 = __fdiv_rn(1.f, do0), i1 = __fdiv_rn(1.f, do1), i2 = __fdiv_rn(1.f, do2);
        float t0x = __fmul_rn(__fsub_rn(-1.f, oo0), i0), t1x = __fmul_rn(__fsub_rn(1.f, oo0), i0);
        float t0y = __fmul_rn(__fsub_rn(-1.f, oo1), i1), t1y = __fmul_rn(__fsub_rn(1.f, oo1), i1);
        float t0z = __fmul_rn(__fsub_rn(-1.f, oo2), i2), t1z = __fmul_rn(__fsub_rn(1.f, oo2), i2);
        float tmin = fmaxf(fmaxf(fminf(t0x, t1x), fminf(t0y, t1y)), fminf(t0z, t1z));
        float tmax = fminf(fminf(fmaxf(t0x, t1x), fmaxf(t0y, t1y)), fmaxf(t0z, t1z));
        bool hit = (tmax > tmin) && (tmax > 0.f);
        float tin = fmaxf(tmin, 0.f);
        float hf  = hit ? 1.f : 0.f;

        float lin = __fdiv_rn((float)lane, 31.0f);
        float zo  = __fadd_rn(tin, __fmul_rn(__fsub_rn(tmax, tin), lin));
        float p0 = __fadd_rn(oo0, __fmul_rn(do0, zo));
        float p1 = __fadd_rn(oo1, __fmul_rn(do1, zo));
        float p2 = __fadd_rn(oo2, __fmul_rn(do2, zo));

        size_t base = ((size_t)(m * N_RAYS + n) * N_SAMPLES + lane) * 3;
        out_pts [base + 0] = __fmul_rn(p0, hf);
        out_pts [base + 1] = __fmul_rn(p1, hf);
        out_pts [base + 2] = __fmul_rn(p2, hf);
        out_dirs[base + 0] = __fmul_rn(do0, hf);
        out_dirs[base + 1] = __fmul_rn(do1, hf);
        out_dirs[base + 2] = __fmul_rn(do2, hf);

        const float* iR = g_iR[m];
        const float* iT = g_iT[m];
        float w0 = __fadd_rn(dot3_fma(p0, p1, p2, iR[0], iR[3], iR[6]), iT[0]);
        float w1 = __fadd_rn(dot3_fma(p0, p1, p2, iR[1], iR[4], iR[7]), iT[1]);
        float w2 = __fadd_rn(dot3_fma(p0, p1, p2, iR[2], iR[5], iR[8]), iT[2]);
        float q0 = __fsub_rn(w0, ox), q1 = __fsub_rn(w1, oy), q2 = __fsub_rn(w2, oz);
        float zw = dot3_fma(q0, q1, q2, dwx, dwy, dwz);

        float v = hit ? zw : MISS;
        mynode = hit ? m : -1;    // warp-uniform: valid for any lane's key

        // 32-bit register bitonic sort of the run. Within-run tie order is
        // irrelevant (same node/mask/value), so no index tie-break needed.
        unsigned k = float_to_ord(v);
        #pragma unroll
        for (int kk = 2; kk <= 32; kk <<= 1) {
            #pragma unroll
            for (int j = kk >> 1; j > 0; j >>= 1) {
                unsigned o = __shfl_xor_sync(0xffffffffu, k, j);
                bool low = (lane & j) == 0;
                bool asc = (lane & kk) == 0;
                unsigned mn = k < o ? k : o;
                unsigned mx = k < o ? o : k;
                k = (low == asc) ? mn : mx;
            }
        }
        myord = k;
        gpos = (m << 5) + lane;
        s_objA[gpos] = myord;
    }
    __syncthreads();

    // ---- payload-free merge tree: 32->64->128->256->512 ----
    if (wid >= 2) gpos = merge_round<5>(s_objA, s_objB, gpos, myord);
    __syncthreads();
    if (wid >= 2) gpos = merge_round<6>(s_objB, s_objA, gpos, myord);
    __syncthreads();
    if (wid >= 2) gpos = merge_round<7>(s_objA, s_objB, gpos, myord);
    __syncthreads();
    if (wid >= 2) gpos = merge_round<8>(s_objB, s_objA, gpos, myord);
    __syncthreads();

    // ---- final merge with the base run + staging ----
    {
        int fin;
        if (wid >= 2) fin = gpos + cnt_le32<N_BASE>(s_base, myord);
        else          fin = tid  + cnt_lt32<N_ZOBJ>(s_objA, myord);
        s_ov[fin] = ord_to_float(myord);
        s_on[fin] = (signed char)mynode;
    }
    __syncthreads();

    // ---- coalesced output ----
    {
        float v = s_ov[tid];
        int nd = (int)s_on[tid];
        size_t ob = (size_t)n * TOTAL + tid;
        out_len [ob] = v;
        out_node[ob] = (float)nd;
        out_mask[ob] = (nd >= 0) ? 1.f : 0.f;
    }
}

// ---------------------------------------------------------------------------
extern "C" void kernel_launch(void* const* d_in, const int* in_sizes, int n_in,
                              void* d_out, int out_size) {
    const float* origins    = (const float*)d_in[0];
    const float* directions = (const float*)d_in[1];
    const float* lengths    = (const float*)d_in[2];
    const float* trafos     = (const float*)d_in[3];
    // d_in[4] = rots_w2o unused (composed linear part identical to trafos@scales)
    const float* scales     = (const float*)d_in[5];

    float* out = (float*)d_out;
    size_t nc = (size_t)N_RAYS * TOTAL;
    float* o_len  = out;
    float* o_node = out + nc;
    float* o_mask = out + 2 * nc;
    float* o_pts  = out + 3 * nc;
    float* o_dirs = o_pts + (size_t)N_OBJ * N_RAYS * N_SAMPLES * 3;

    precompute_kernel<<<1, 32>>>(trafos, scales);
    fused_kernel<<<N_RAYS, TOTAL>>>(origins, directions, lengths,
                                    o_len, o_node, o_mask, o_pts, o_dirs);
}